// round 4
// baseline (speedup 1.0000x reference)
#include <cuda_runtime.h>
#include <cuda_bf16.h>

// GENConv softmax_sg + MLP via CSR (counting sort by dst).
// h[n] = MLP( sum m*exp(b*m) / sum exp(b*m) ), m = relu(x[src])+eps.
// Fused kernel: warp-per-node gather-reduce (phase A) + thread-per-node
// shuffle-free register MLP (phase B). edge_index is int32.

#define EPS 1e-7f
#define MAXN 131072
#define MAXE 2097152

__device__ int g_deg[MAXN];
__device__ int g_off[MAXN];
__device__ int g_cur[MAXN];
__device__ int g_part[256];
__device__ int g_srcs[MAXE];

__global__ void k_zero(int N) {
    int i = blockIdx.x * blockDim.x + threadIdx.x;
    if (i < N) g_deg[i] = 0;
}

__global__ void k_hist(const int* __restrict__ ei, int E) {
    int e = blockIdx.x * blockDim.x + threadIdx.x;
    if (e < E) atomicAdd(&g_deg[ei[e]], 1);
}

__global__ void k_scan1(int N) {
    __shared__ int ws[32];
    int tid = threadIdx.x;
    int g = blockIdx.x * 1024 + tid;
    int v = (g < N) ? g_deg[g] : 0;
    int x = v;
#pragma unroll
    for (int o = 1; o < 32; o <<= 1) {
        int t = __shfl_up_sync(0xffffffffu, x, o);
        if ((tid & 31) >= o) x += t;
    }
    if ((tid & 31) == 31) ws[tid >> 5] = x;
    __syncthreads();
    if (tid < 32) {
        int w = ws[tid];
        int y = w;
#pragma unroll
        for (int o = 1; o < 32; o <<= 1) {
            int t = __shfl_up_sync(0xffffffffu, y, o);
            if (tid >= o) y += t;
        }
        ws[tid] = y - w;
    }
    __syncthreads();
    int excl = x - v + ws[tid >> 5];
    if (g < N) g_off[g] = excl;
    if (tid == 1023) g_part[blockIdx.x] = excl + v;
}

__global__ void k_scan2(int NB) {
    __shared__ int ws[8];
    int tid = threadIdx.x;
    int v = (tid < NB) ? g_part[tid] : 0;
    int x = v;
#pragma unroll
    for (int o = 1; o < 32; o <<= 1) {
        int t = __shfl_up_sync(0xffffffffu, x, o);
        if ((tid & 31) >= o) x += t;
    }
    if ((tid & 31) == 31) ws[tid >> 5] = x;
    __syncthreads();
    if (tid < 8) {
        int w = ws[tid];
        int y = w;
#pragma unroll
        for (int o = 1; o < 8; o <<= 1) {
            int t = __shfl_up_sync(0xffu, y, o);
            if (tid >= o) y += t;
        }
        ws[tid] = y - w;
    }
    __syncthreads();
    int excl = x - v + ws[tid >> 5];
    if (tid < NB) g_part[tid] = excl;
}

__global__ void k_scan3(int N) {
    int g = blockIdx.x * blockDim.x + threadIdx.x;
    if (g < N) {
        int o = g_off[g] + g_part[g >> 10];
        g_off[g] = o;
        g_cur[g] = o;
    }
}

__global__ void k_place(const int* __restrict__ ei, int E) {
    int e = blockIdx.x * blockDim.x + threadIdx.x;
    if (e < E) {
        int dst = ei[e];
        int src = ei[E + e];
        int p = atomicAdd(&g_cur[dst], 1);
        g_srcs[p] = src;
    }
}

// ---------------- fused aggregate + MLP ----------------
// Block: 128 threads = 4 warps, handles 128 nodes.
// Phase A: warp w aggregates nodes [w*32, w*32+32), lane = channel, h -> smem.
// Phase B: thread t runs the full MLP for node t in registers (no shuffles).

#define NPB 128   // nodes per block

__global__ void __launch_bounds__(NPB) k_fused(
        const float* __restrict__ xp,
        const float* __restrict__ beta_p,
        const float* __restrict__ W1, const float* __restrict__ b1,
        const float* __restrict__ W2, const float* __restrict__ b2,
        float* __restrict__ out, int N) {
    __shared__ float hbuf[NPB * 33];      // padded: (t*33+i)%32 conflict-free
    __shared__ float W1T[64 * 32];        // W1T[k][i] = W1[i][k]
    __shared__ float W2s[64 * 32];        // W2[k][j], rows contiguous in j
    __shared__ float b1s[64];
    __shared__ float b2s[32];

    int tid = threadIdx.x;
    for (int i = tid; i < 2048; i += NPB) {
        int r = i >> 6, c = i & 63;       // W1[r][c]
        W1T[c * 32 + r] = W1[i];
        W2s[i] = W2[i];
    }
    if (tid < 64) b1s[tid] = b1[tid];
    if (tid < 32) b2s[tid] = b2[tid];

    const float beta = __ldg(beta_p);
    int lane = tid & 31;
    int warp = tid >> 5;
    int nodeBase = blockIdx.x * NPB;

    // prefetch this warp's 32 node descriptors across lanes
    int myNode = nodeBase + warp * 32 + lane;
    int myOff = 0, myDeg = 0;
    if (myNode < N) { myOff = g_off[myNode]; myDeg = g_deg[myNode]; }

    for (int t = 0; t < 32; t++) {
        int start = __shfl_sync(0xffffffffu, myOff, t);
        int deg   = __shfl_sync(0xffffffffu, myDeg, t);

        float num = 0.f, den = 0.f;
        int p = 0;
        for (; p + 8 <= deg; p += 8) {
            int s = (lane < 8) ? g_srcs[start + p + lane] : 0;
            int si[8];
#pragma unroll
            for (int j = 0; j < 8; j++) si[j] = __shfl_sync(0xffffffffu, s, j);
            float xv[8];
#pragma unroll
            for (int j = 0; j < 8; j++) xv[j] = __ldg(&xp[si[j] * 32 + lane]);
#pragma unroll
            for (int j = 0; j < 8; j++) {
                float m = fmaxf(xv[j], 0.f) + EPS;
                float e = __expf(beta * m);
                num = fmaf(m, e, num);
                den += e;
            }
        }
        int rem = deg - p;   // uniform across warp
        if (rem > 0) {
            int s = (lane < rem) ? g_srcs[start + p + lane] : 0;
            float xv[8];
#pragma unroll
            for (int j = 0; j < 8; j++) {
                int sj = __shfl_sync(0xffffffffu, s, j);
                xv[j] = (j < rem) ? __ldg(&xp[sj * 32 + lane]) : 0.f;
            }
#pragma unroll
            for (int j = 0; j < 8; j++) {
                if (j < rem) {
                    float m = fmaxf(xv[j], 0.f) + EPS;
                    float e = __expf(beta * m);
                    num = fmaf(m, e, num);
                    den += e;
                }
            }
        }
        float h = (den > 0.f) ? num / den : 0.f;
        hbuf[(warp * 32 + t) * 33 + lane] = h;
    }
    __syncthreads();

    // Phase B: thread tid owns node nodeBase+tid.
    float h[32];
#pragma unroll
    for (int i = 0; i < 32; i++) h[i] = hbuf[tid * 33 + i];
    float o[32];
#pragma unroll
    for (int j = 0; j < 32; j++) o[j] = b2s[j];

#pragma unroll 2
    for (int k = 0; k < 64; k++) {
        float a = b1s[k];
        const float4* w1r = (const float4*)&W1T[k * 32];
#pragma unroll
        for (int i = 0; i < 8; i++) {
            float4 w = w1r[i];
            a = fmaf(h[4 * i + 0], w.x, a);
            a = fmaf(h[4 * i + 1], w.y, a);
            a = fmaf(h[4 * i + 2], w.z, a);
            a = fmaf(h[4 * i + 3], w.w, a);
        }
        a = fmaxf(a, 0.f);
        const float4* w2r = (const float4*)&W2s[k * 32];
#pragma unroll
        for (int j = 0; j < 8; j++) {
            float4 w = w2r[j];
            o[4 * j + 0] = fmaf(a, w.x, o[4 * j + 0]);
            o[4 * j + 1] = fmaf(a, w.y, o[4 * j + 1]);
            o[4 * j + 2] = fmaf(a, w.z, o[4 * j + 2]);
            o[4 * j + 3] = fmaf(a, w.w, o[4 * j + 3]);
        }
    }

    int n = nodeBase + tid;
    if (n < N) {
        float4* op = (float4*)(out + (size_t)n * 32);
#pragma unroll
        for (int j = 0; j < 8; j++)
            op[j] = make_float4(o[4 * j], o[4 * j + 1], o[4 * j + 2], o[4 * j + 3]);
    }
}

extern "C" void kernel_launch(void* const* d_in, const int* in_sizes, int n_in,
                              void* d_out, int out_size) {
    const float* x    = (const float*)d_in[0];
    const int*   ei   = (const int*)d_in[1];
    const float* beta = (const float*)d_in[2];
    const float* W1   = (const float*)d_in[3];
    const float* b1   = (const float*)d_in[4];
    const float* W2   = (const float*)d_in[5];
    const float* b2   = (const float*)d_in[6];
    float*       out  = (float*)d_out;

    int N = in_sizes[0] / 32;   // 100000
    int E = in_sizes[1] / 2;    // 1600000
    int NB = (N + 1023) / 1024;

    k_zero<<<(N + 255) / 256, 256>>>(N);
    k_hist<<<(E + 255) / 256, 256>>>(ei, E);
    k_scan1<<<NB, 1024>>>(N);
    k_scan2<<<1, 256>>>(NB);
    k_scan3<<<(N + 255) / 256, 256>>>(N);
    k_place<<<(E + 255) / 256, 256>>>(ei, E);
    k_fused<<<(N + NPB - 1) / NPB, NPB>>>(x, beta, W1, b1, W2, b2, out, N);
}